// round 11
// baseline (speedup 1.0000x reference)
#include <cuda_runtime.h>
#include <stdint.h>

// ParallelTransport: out[e, c, :] = R(rho[e]) @ x[row[e], c, :]
// x: (1, N, 32, 2) fp32 ; edge_index: (2, E) int32 ; rho: (E,) fp32
// out: (1, E, 32, 2) fp32
//
// R11 = R10 (best: 63.6 us) + L1::no_allocate on the x gathers.
// 16 threads per edge, one float4 per thread, ITER=4 slots per thread in
// batched phases (MLP=4 on the L2-resident 12.8 MB x table). Gather loads
// skip L1 allocation (random rows, ~no L1 reuse; L1tex was the hottest
// stage at 69.8%). Streaming stores keep x resident in L2.

#define ITER 4
#define TPB  256

__device__ __forceinline__ float4 ldg_noL1(const float4* p) {
    float4 v;
    asm volatile("ld.global.nc.L1::no_allocate.v4.f32 {%0,%1,%2,%3}, [%4];"
                 : "=f"(v.x), "=f"(v.y), "=f"(v.z), "=f"(v.w)
                 : "l"(p));
    return v;
}

__global__ void __launch_bounds__(TPB)
pt_kernel(const float* __restrict__ x,
          const int* __restrict__ row,
          const float* __restrict__ rho,
          float4* __restrict__ out,
          unsigned total /* E * 16 float4 slots, < 2^31 */)
{
    unsigned base = blockIdx.x * (TPB * ITER) + threadIdx.x;

    bool   ok[ITER];
    int    r[ITER];
    float  rv[ITER];
    float4 v[ITER];

    // Phase 1: index + rho loads (L1-broadcast within 16-lane groups)
    #pragma unroll
    for (int i = 0; i < ITER; i++) {
        unsigned slot = base + i * TPB;
        unsigned e = slot >> 4;
        ok[i] = slot < total;
        r[i]  = ok[i] ? __ldg(&row[e]) : 0;
        rv[i] = ok[i] ? __ldg(&rho[e]) : 0.0f;
    }

    // Phase 2: dependent gathers — 4 independent chains, no L1 allocation
    #pragma unroll
    for (int i = 0; i < ITER; i++) {
        unsigned sub = (base + i * TPB) & 15u;
        v[i] = ldg_noL1(reinterpret_cast<const float4*>(x)
                        + ((unsigned)r[i] * 16u + sub));
    }

    // Phase 3: rotate + streaming store
    #pragma unroll
    for (int i = 0; i < ITER; i++) {
        if (!ok[i]) continue;
        float s, c;
        __sincosf(rv[i], &s, &c);
        float4 o;
        o.x = fmaf(c, v[i].x, -s * v[i].y);
        o.y = fmaf(s, v[i].x,  c * v[i].y);
        o.z = fmaf(c, v[i].z, -s * v[i].w);
        o.w = fmaf(s, v[i].z,  c * v[i].w);
        __stcs(&out[base + i * TPB], o);
    }
}

extern "C" void kernel_launch(void* const* d_in, const int* in_sizes, int n_in,
                              void* d_out, int out_size)
{
    const float* x    = (const float*)d_in[0];
    const int*   eidx = (const int*)d_in[1];   // (2, E): first E entries = row
    const float* rho  = (const float*)d_in[2];

    unsigned E = (unsigned)in_sizes[2];
    unsigned total = E * 16u;                  // float4 slots

    unsigned per_block = TPB * ITER;
    unsigned blocks = (total + per_block - 1) / per_block;

    pt_kernel<<<blocks, TPB>>>(x, eidx, rho, (float4*)d_out, total);
}

// round 12
// speedup vs baseline: 1.0305x; 1.0305x over previous
#include <cuda_runtime.h>
#include <stdint.h>

// ParallelTransport: out[e, c, :] = R(rho[e]) @ x[row[e], c, :]
// x: (1, N, 32, 2) fp32 ; edge_index: (2, E) int32 ; rho: (E,) fp32
// out: (1, E, 32, 2) fp32
//
// R12 = R10 (best: 63.6 us) with default store policy instead of __stcs.
// 16 threads per edge, one float4 per thread, ITER=4 slots per thread in
// batched phases: all index/rho loads, then 4 independent gathers (MLP=4,
// x table is L2-resident at 12.8 MB), then rotate + store. x cannot be
// evicted by the write stream anyway (126 MB L2), so evict-first stores
// were unnecessary and may hurt LTS write coalescing.

#define ITER 4
#define TPB  256

__global__ void __launch_bounds__(TPB)
pt_kernel(const float* __restrict__ x,
          const int* __restrict__ row,
          const float* __restrict__ rho,
          float4* __restrict__ out,
          unsigned total /* E * 16 float4 slots, < 2^31 */)
{
    unsigned base = blockIdx.x * (TPB * ITER) + threadIdx.x;

    bool   ok[ITER];
    int    r[ITER];
    float  rv[ITER];
    float4 v[ITER];

    // Phase 1: index + rho loads (L1-broadcast within 16-lane groups)
    #pragma unroll
    for (int i = 0; i < ITER; i++) {
        unsigned slot = base + i * TPB;
        unsigned e = slot >> 4;
        ok[i] = slot < total;
        r[i]  = ok[i] ? __ldg(&row[e]) : 0;
        rv[i] = ok[i] ? __ldg(&rho[e]) : 0.0f;
    }

    // Phase 2: dependent gathers — 4 independent chains in flight
    #pragma unroll
    for (int i = 0; i < ITER; i++) {
        unsigned sub = (base + i * TPB) & 15u;
        v[i] = __ldg(reinterpret_cast<const float4*>(x)
                     + ((unsigned)r[i] * 16u + sub));
    }

    // Phase 3: rotate + store (default policy)
    #pragma unroll
    for (int i = 0; i < ITER; i++) {
        if (!ok[i]) continue;
        float s, c;
        __sincosf(rv[i], &s, &c);
        float4 o;
        o.x = fmaf(c, v[i].x, -s * v[i].y);
        o.y = fmaf(s, v[i].x,  c * v[i].y);
        o.z = fmaf(c, v[i].z, -s * v[i].w);
        o.w = fmaf(s, v[i].z,  c * v[i].w);
        out[base + i * TPB] = o;
    }
}

extern "C" void kernel_launch(void* const* d_in, const int* in_sizes, int n_in,
                              void* d_out, int out_size)
{
    const float* x    = (const float*)d_in[0];
    const int*   eidx = (const int*)d_in[1];   // (2, E): first E entries = row
    const float* rho  = (const float*)d_in[2];

    unsigned E = (unsigned)in_sizes[2];
    unsigned total = E * 16u;                  // float4 slots

    unsigned per_block = TPB * ITER;
    unsigned blocks = (total + per_block - 1) / per_block;

    pt_kernel<<<blocks, TPB>>>(x, eidx, rho, (float4*)d_out, total);
}